// round 1
// baseline (speedup 1.0000x reference)
#include <cuda_runtime.h>

#define BATCH 32
#define FEAT  1024
#define PROJ  256
#define NSUP  8192
#define NCLS  1000

// ---- scratch (no allocations allowed; __device__ globals) ----
__device__ float g_xq[BATCH * PROJ];          // 32 KB
__device__ float g_sxp[NSUP * PROJ];          // 8 MB
__device__ float g_ssq[NSUP];                 // 32 KB
__device__ float g_logits[BATCH * NSUP];      // 1 MB
__device__ int   g_sy_is64;

// packed fp32x2 FMA (Blackwell): d = a*b + c on two lanes of a 64-bit pair
__device__ __forceinline__ unsigned long long ffma2(unsigned long long a,
                                                    unsigned long long b,
                                                    unsigned long long c) {
    unsigned long long d;
    asm("fma.rn.f32x2 %0, %1, %2, %3;" : "=l"(d) : "l"(a), "l"(b), "l"(c));
    return d;
}
__device__ __forceinline__ float ull_lo(unsigned long long v) {
    return __uint_as_float((unsigned)(v & 0xffffffffULL));
}
__device__ __forceinline__ float ull_hi(unsigned long long v) {
    return __uint_as_float((unsigned)(v >> 32));
}

// ---------------------------------------------------------------------------
// K0: detect whether sy is int64 (high words of first 4096 entries all zero)
// or int32. Safe: reads exactly 8192 32-bit words (the minimum buffer size).
// ---------------------------------------------------------------------------
__global__ void k_detect(const unsigned* __restrict__ w) {
    __shared__ int nz;
    if (threadIdx.x == 0) nz = 0;
    __syncthreads();
    int f = 0;
    for (int i = threadIdx.x; i < 4096; i += 256)
        if (w[2 * i + 1] != 0u) f = 1;
    if (f) atomicOr(&nz, 1);
    __syncthreads();
    if (threadIdx.x == 0) g_sy_is64 = (nz == 0) ? 1 : 0;
}

// ---------------------------------------------------------------------------
// K1: xq = x @ W   (32 x 256), split-K with atomics for latency hiding
// ---------------------------------------------------------------------------
__global__ void k_zero_xq(void) {
    g_xq[blockIdx.x * 1024 + threadIdx.x] = 0.f;
}

__global__ void k_xq(const float* __restrict__ x, const float* __restrict__ W) {
    __shared__ float xs[256];
    const int b  = blockIdx.x;
    const int kc = blockIdx.y * 256;
    const int p  = threadIdx.x;
    xs[threadIdx.x] = x[b * FEAT + kc + threadIdx.x];
    __syncthreads();
    float acc = 0.f;
#pragma unroll 16
    for (int k = 0; k < 256; k++)
        acc = fmaf(xs[k], W[(size_t)(kc + k) * PROJ + p], acc);
    atomicAdd(&g_xq[b * PROJ + p], acc);
}

// ---------------------------------------------------------------------------
// K2: sxp = sx @ W   (8192 x 256) — the dominant GEMM.
// Tile 128(S) x 64(P), K-chunk 16, 256 threads, 8x4 microtile packed as
// f32x2 pairs along S. B is stored DUPLICATED in smem so b-pairs load
// directly as 64-bit values (no pack MOVs in the inner loop).
// Inner loop per k: 4x LDS.128 + 16x FFMA2  -> FMA-pipe bound.
// ---------------------------------------------------------------------------
__global__ void __launch_bounds__(256, 2)
k_sxp(const float* __restrict__ sx, const float* __restrict__ W) {
    __shared__ __align__(16) float As[16][132];   // A transposed: As[k][s]
    __shared__ __align__(16) float Bsd[16][136];  // B duplicated: [k][2p],[k][2p+1]
    const int bs  = blockIdx.x * 128;
    const int bp  = blockIdx.y * 64;
    const int tid = threadIdx.x;
    const int tx  = tid & 15;   // proj group (4 cols)
    const int ty  = tid >> 4;   // support group (8 rows)

    unsigned long long c2[4][4];
#pragma unroll
    for (int i = 0; i < 4; i++)
#pragma unroll
        for (int j = 0; j < 4; j++) c2[i][j] = 0ULL;

    for (int k0 = 0; k0 < FEAT; k0 += 16) {
        // load A tile (128 x 16) transposed
#pragma unroll
        for (int r = 0; r < 2; r++) {
            int idx = tid + r * 256;
            int row = idx >> 2;
            int kq  = (idx & 3) << 2;
            float4 v = *(const float4*)(sx + (size_t)(bs + row) * FEAT + k0 + kq);
            As[kq + 0][row] = v.x; As[kq + 1][row] = v.y;
            As[kq + 2][row] = v.z; As[kq + 3][row] = v.w;
        }
        // load B tile (16 x 64) duplicated
        {
            int kr = tid >> 4;
            int pq = (tid & 15) << 2;
            float4 v  = *(const float4*)(W + (size_t)(k0 + kr) * PROJ + bp + pq);
            float4 d0 = make_float4(v.x, v.x, v.y, v.y);
            float4 d1 = make_float4(v.z, v.z, v.w, v.w);
            *(float4*)&Bsd[kr][2 * pq]     = d0;
            *(float4*)&Bsd[kr][2 * pq + 4] = d1;
        }
        __syncthreads();
#pragma unroll
        for (int k = 0; k < 16; k++) {
            ulonglong2 av0 = *(const ulonglong2*)&As[k][ty * 8];
            ulonglong2 av1 = *(const ulonglong2*)&As[k][ty * 8 + 4];
            ulonglong2 bv0 = *(const ulonglong2*)&Bsd[k][tx * 8];
            ulonglong2 bv1 = *(const ulonglong2*)&Bsd[k][tx * 8 + 4];
            unsigned long long a2[4] = {av0.x, av0.y, av1.x, av1.y};
            unsigned long long b2[4] = {bv0.x, bv0.y, bv1.x, bv1.y};
#pragma unroll
            for (int i = 0; i < 4; i++)
#pragma unroll
                for (int j = 0; j < 4; j++)
                    c2[i][j] = ffma2(a2[i], b2[j], c2[i][j]);
        }
        __syncthreads();
    }
    // write: c2[i][j] holds rows (ty*8+2i, ty*8+2i+1), col bp+tx*4+j
#pragma unroll
    for (int i = 0; i < 4; i++) {
#pragma unroll
        for (int half = 0; half < 2; half++) {
            int row = bs + ty * 8 + i * 2 + half;
            float4 o;
            o.x = half ? ull_hi(c2[i][0]) : ull_lo(c2[i][0]);
            o.y = half ? ull_hi(c2[i][1]) : ull_lo(c2[i][1]);
            o.z = half ? ull_hi(c2[i][2]) : ull_lo(c2[i][2]);
            o.w = half ? ull_hi(c2[i][3]) : ull_lo(c2[i][3]);
            *(float4*)(g_sxp + (size_t)row * PROJ + bp + tx * 4) = o;
        }
    }
}

// ---------------------------------------------------------------------------
// K3: ssq[j] = ||sxp_j||^2
// ---------------------------------------------------------------------------
__global__ void k_ssq(void) {
    int j    = blockIdx.x * 8 + (threadIdx.x >> 5);
    int lane = threadIdx.x & 31;
    const float4* row = (const float4*)(g_sxp + (size_t)j * PROJ);
    float s = 0.f;
#pragma unroll
    for (int q = 0; q < 2; q++) {
        float4 v = row[lane + 32 * q];
        s += v.x * v.x + v.y * v.y + v.z * v.z + v.w * v.w;
    }
#pragma unroll
    for (int o = 16; o; o >>= 1) s += __shfl_xor_sync(0xffffffffu, s, o);
    if (lane == 0) g_ssq[j] = s;
}

// ---------------------------------------------------------------------------
// K4: logits[b][j] = 2 * xq_b . sxp_j - ssq_j   (x_sq dropped: softmax-shift
// invariant). Tile: all 32 batch x 128 support per block, K=256.
// ---------------------------------------------------------------------------
__global__ void __launch_bounds__(256) k_logits(void) {
    __shared__ __align__(16) float xqT[PROJ][33];  // transposed xq
    __shared__ __align__(16) float Ss[16][132];    // sxp tile transposed
    const int js  = blockIdx.x * 128;
    const int tid = threadIdx.x;
    const int tx  = tid & 15;   // support group (8)
    const int ty  = tid >> 4;   // batch group (2)

    for (int i = tid; i < BATCH * PROJ; i += 256)
        xqT[i & 255][i >> 8] = g_xq[i];

    float c[2][8];
#pragma unroll
    for (int i = 0; i < 2; i++)
#pragma unroll
        for (int j = 0; j < 8; j++) c[i][j] = 0.f;

    for (int k0 = 0; k0 < PROJ; k0 += 16) {
        __syncthreads();
#pragma unroll
        for (int r = 0; r < 2; r++) {
            int idx = tid + r * 256;
            int row = idx >> 2;
            int kq  = (idx & 3) << 2;
            float4 v = *(const float4*)(g_sxp + (size_t)(js + row) * PROJ + k0 + kq);
            Ss[kq + 0][row] = v.x; Ss[kq + 1][row] = v.y;
            Ss[kq + 2][row] = v.z; Ss[kq + 3][row] = v.w;
        }
        __syncthreads();
#pragma unroll
        for (int k = 0; k < 16; k++) {
            float a0 = xqT[k0 + k][ty * 2];
            float a1 = xqT[k0 + k][ty * 2 + 1];
            float4 s0 = *(const float4*)&Ss[k][tx * 8];
            float4 s1 = *(const float4*)&Ss[k][tx * 8 + 4];
            float sv[8] = {s0.x, s0.y, s0.z, s0.w, s1.x, s1.y, s1.z, s1.w};
#pragma unroll
            for (int j = 0; j < 8; j++) {
                c[0][j] = fmaf(a0, sv[j], c[0][j]);
                c[1][j] = fmaf(a1, sv[j], c[1][j]);
            }
        }
    }
#pragma unroll
    for (int bi = 0; bi < 2; bi++) {
        int b = ty * 2 + bi;
#pragma unroll
        for (int h = 0; h < 2; h++) {
            int j0 = tx * 8 + h * 4;
            float4 o;
            o.x = 2.f * c[bi][h * 4 + 0] - g_ssq[js + j0 + 0];
            o.y = 2.f * c[bi][h * 4 + 1] - g_ssq[js + j0 + 1];
            o.z = 2.f * c[bi][h * 4 + 2] - g_ssq[js + j0 + 2];
            o.w = 2.f * c[bi][h * 4 + 3] - g_ssq[js + j0 + 3];
            *(float4*)(g_logits + (size_t)b * NSUP + js + j0) = o;
        }
    }
}

// ---------------------------------------------------------------------------
// K5: per-row softmax + class scatter + log. One block per batch row.
// ---------------------------------------------------------------------------
__global__ void __launch_bounds__(1024) k_out(const int* __restrict__ syw,
                                              float* __restrict__ out) {
    const int b = blockIdx.x;
    __shared__ float red[32];
    __shared__ float cls[NCLS];
    const int tid  = threadIdx.x;
    const int warp = tid >> 5, lane = tid & 31;

    for (int c = tid; c < NCLS; c += 1024) cls[c] = 0.f;

    const float* lr = g_logits + (size_t)b * NSUP;
    float l[8];
    float m = -3.4e38f;
#pragma unroll
    for (int q = 0; q < 8; q++) {
        l[q] = lr[q * 1024 + tid];
        m = fmaxf(m, l[q]);
    }
#pragma unroll
    for (int o = 16; o; o >>= 1) m = fmaxf(m, __shfl_xor_sync(0xffffffffu, m, o));
    if (lane == 0) red[warp] = m;
    __syncthreads();
    if (warp == 0) {
        float v = red[lane];
#pragma unroll
        for (int o = 16; o; o >>= 1) v = fmaxf(v, __shfl_xor_sync(0xffffffffu, v, o));
        if (lane == 0) red[0] = v;
    }
    __syncthreads();
    m = red[0];
    __syncthreads();

    float e[8];
    float s = 0.f;
#pragma unroll
    for (int q = 0; q < 8; q++) {
        e[q] = expf(l[q] - m);
        s += e[q];
    }
#pragma unroll
    for (int o = 16; o; o >>= 1) s += __shfl_xor_sync(0xffffffffu, s, o);
    if (lane == 0) red[warp] = s;
    __syncthreads();
    if (warp == 0) {
        float v = red[lane];
#pragma unroll
        for (int o = 16; o; o >>= 1) v += __shfl_xor_sync(0xffffffffu, v, o);
        if (lane == 0) red[0] = v;
    }
    __syncthreads();
    const float invZ = 1.f / red[0];
    const int is64 = g_sy_is64;

#pragma unroll
    for (int q = 0; q < 8; q++) {
        int j = q * 1024 + tid;
        int cidx = is64 ? syw[2 * j] : syw[j];
        atomicAdd(&cls[cidx], e[q]);
    }
    __syncthreads();
    for (int c = tid; c < NCLS; c += 1024)
        out[b * NCLS + c] = logf(cls[c] * invZ + 1e-12f);
}

// ---------------------------------------------------------------------------
extern "C" void kernel_launch(void* const* d_in, const int* in_sizes, int n_in,
                              void* d_out, int out_size) {
    const float* x = nullptr;
    const float* sx = nullptr;
    const float* W = nullptr;
    const void*  sy = nullptr;
    for (int i = 0; i < n_in; i++) {
        switch (in_sizes[i]) {
            case BATCH * FEAT: x  = (const float*)d_in[i]; break;
            case NSUP * FEAT:  sx = (const float*)d_in[i]; break;
            case FEAT * PROJ:  W  = (const float*)d_in[i]; break;
            case NSUP:         sy = d_in[i];               break;
            default: break;
        }
    }
    float* out = (float*)d_out;

    k_detect<<<1, 256>>>((const unsigned*)sy);
    k_zero_xq<<<8, 1024>>>();
    {
        dim3 g(BATCH, FEAT / 256);
        k_xq<<<g, 256>>>(x, W);
    }
    {
        dim3 g(NSUP / 128, PROJ / 64);
        k_sxp<<<g, 256>>>(sx, W);
    }
    k_ssq<<<NSUP / 8, 256>>>();
    k_logits<<<NSUP / 128, 256>>>();
    k_out<<<BATCH, 1024>>>((const int*)sy, out);
}

// round 3
// speedup vs baseline: 2.5399x; 2.5399x over previous
#include <cuda_runtime.h>
#include <cuda_bf16.h>
#include <cstdint>

#define BATCH 32
#define FEAT  1024
#define PROJ  256
#define NSUP  8192
#define NCLS  1000

// ---- scratch (no allocations allowed; __device__ globals) ----
__device__ float g_xq[BATCH * PROJ];
__device__ float g_sxp[NSUP * PROJ];             // 8 MB
__device__ float g_ssq[NSUP];
__device__ float g_logits[BATCH * NSUP];         // 1 MB
__device__ int   g_sy_is64;
__device__ __nv_bfloat16 g_wt[PROJ * 2 * FEAT];  // W^T hi/lo interleaved [256][2048]

__device__ __forceinline__ uint32_t smem_u32(const void* p) {
    uint32_t a;
    asm("{ .reg .u64 t; cvta.to.shared.u64 t, %1; cvt.u32.u64 %0, t; }"
        : "=r"(a) : "l"(p));
    return a;
}

// ---------------------------------------------------------------------------
// K0: detect int64 vs int32 sy
// ---------------------------------------------------------------------------
__global__ void k_detect(const unsigned* __restrict__ w) {
    __shared__ int nz;
    if (threadIdx.x == 0) nz = 0;
    __syncthreads();
    int f = 0;
    for (int i = threadIdx.x; i < 4096; i += 256)
        if (w[2 * i + 1] != 0u) f = 1;
    if (f) atomicOr(&nz, 1);
    __syncthreads();
    if (threadIdx.x == 0) g_sy_is64 = (nz == 0) ? 1 : 0;
}

// ---------------------------------------------------------------------------
// K_wt: transpose + hi/lo-split W[1024][256] -> g_wt[256][2048] interleaved
// ---------------------------------------------------------------------------
__global__ void k_wt(const float* __restrict__ W) {
    __shared__ float t[32][33];
    const int kb = blockIdx.x * 32, nb = blockIdx.y * 32;
    const int tx = threadIdx.x & 31, ty = threadIdx.x >> 5;  // ty 0..7
#pragma unroll
    for (int r = 0; r < 4; r++) {
        int k = kb + ty + r * 8;
        t[ty + r * 8][tx] = W[(size_t)k * PROJ + nb + tx];
    }
    __syncthreads();
    __nv_bfloat162* out2 = (__nv_bfloat162*)g_wt;
#pragma unroll
    for (int r = 0; r < 4; r++) {
        int n = nb + ty + r * 8;
        float a = t[tx][ty + r * 8];
        __nv_bfloat16 h = __float2bfloat16(a);
        float lf = a - __bfloat162float(h);
        out2[(size_t)n * FEAT + kb + tx] =
            __floats2bfloat162_rn(__bfloat162float(h), lf);
    }
}

// ---------------------------------------------------------------------------
// K1: xq = x @ W (32 x 256), split-K with atomics
// ---------------------------------------------------------------------------
__global__ void k_zero_xq(void) { g_xq[blockIdx.x * 1024 + threadIdx.x] = 0.f; }

__global__ void k_xq(const float* __restrict__ x, const float* __restrict__ W) {
    __shared__ float xs[256];
    const int b = blockIdx.x, kc = blockIdx.y * 256, p = threadIdx.x;
    xs[threadIdx.x] = x[b * FEAT + kc + threadIdx.x];
    __syncthreads();
    float acc = 0.f;
#pragma unroll 16
    for (int k = 0; k < 256; k++)
        acc = fmaf(xs[k], W[(size_t)(kc + k) * PROJ + p], acc);
    atomicAdd(&g_xq[b * PROJ + p], acc);
}

// ---------------------------------------------------------------------------
// K2: sxp = sx @ W via mma.sync bf16 with hi/lo K-doubling (K'=2048).
// CTA tile 128(M) x 128(N), grid (64, 2). 256 thr = 8 warps (4M x 2N),
// each warp 32(M) x 64(N). K-chunk = 16 original k = 32 expanded bf16.
// Smem rows pitch 80 B -> (5r+u) mod 8 permutation => ldmatrix conflict-free.
// ---------------------------------------------------------------------------
#define PITCH 40   // bf16 per smem row (80 bytes)

__global__ void __launch_bounds__(256, 2)
k_sxp_hmma(const float* __restrict__ sx) {
    __shared__ __align__(16) __nv_bfloat16 As[2][128 * PITCH];
    __shared__ __align__(16) __nv_bfloat16 Bs[2][128 * PITCH];

    const int tid  = threadIdx.x;
    const int lane = tid & 31;
    const int wid  = tid >> 5;
    const int wm   = wid & 3;        // warp M block (32 rows)
    const int wn   = wid >> 2;       // warp N block (64 cols)
    const int bs   = blockIdx.x * 128;
    const int bn   = blockIdx.y * 128;

    const uint32_t a_base[2] = {smem_u32(As[0]), smem_u32(As[1])};
    const uint32_t b_base[2] = {smem_u32(Bs[0]), smem_u32(Bs[1])};

    // per-thread load coords (2 iters each, i = p*256+tid): row=i>>2, q=i&3
    const int lr0 = tid >> 2,          lq0 = tid & 3;
    const int lr1 = (256 + tid) >> 2,  lq1 = (256 + tid) & 3;

    const __nv_bfloat162* wt2 = (const __nv_bfloat162*)g_wt;

    float c[2][8][4];
#pragma unroll
    for (int t = 0; t < 2; t++)
#pragma unroll
        for (int n = 0; n < 8; n++)
#pragma unroll
            for (int e = 0; e < 4; e++) c[t][n][e] = 0.f;

    // ldmatrix lane address components
    const int grp  = lane >> 3;
    const int rsel = lane & 7;
    // A: matrices (m0..7,klo),(m8..15,klo),(m0..7,khi),(m8..15,khi)
    const int a_row_off = ((grp & 1) << 3) + rsel;   // + t*16 + wm*32
    const int a_u_off   = (grp >> 1) & 1;            // + 2*ks
    // B: matrices (n0..7,klo),(n0..7,khi),(n8..15,klo),(n8..15,khi)
    const int b_row_off = ((grp >> 1) << 3) + rsel;  // + np*16 + wn*64
    const int b_u_off   = grp & 1;                   // + 2*ks

    // ---- helpers as lambdas (inlined) ----
    auto convert_pack = [](float4 v) -> uint4 {
        __nv_bfloat16 h0 = __float2bfloat16(v.x);
        __nv_bfloat16 h1 = __float2bfloat16(v.y);
        __nv_bfloat16 h2 = __float2bfloat16(v.z);
        __nv_bfloat16 h3 = __float2bfloat16(v.w);
        __nv_bfloat162 p0 = __floats2bfloat162_rn(__bfloat162float(h0), v.x - __bfloat162float(h0));
        __nv_bfloat162 p1 = __floats2bfloat162_rn(__bfloat162float(h1), v.y - __bfloat162float(h1));
        __nv_bfloat162 p2 = __floats2bfloat162_rn(__bfloat162float(h2), v.z - __bfloat162float(h2));
        __nv_bfloat162 p3 = __floats2bfloat162_rn(__bfloat162float(h3), v.w - __bfloat162float(h3));
        return make_uint4(*(uint32_t*)&p0, *(uint32_t*)&p1,
                          *(uint32_t*)&p2, *(uint32_t*)&p3);
    };

    // prologue: chunk 0
    {
        float4 av0 = *(const float4*)(sx + (size_t)(bs + lr0) * FEAT + lq0 * 4);
        float4 av1 = *(const float4*)(sx + (size_t)(bs + lr1) * FEAT + lq1 * 4);
        uint4 bv0 = *(const uint4*)(wt2 + (size_t)(bn + lr0) * FEAT + lq0 * 4);
        uint4 bv1 = *(const uint4*)(wt2 + (size_t)(bn + lr1) * FEAT + lq1 * 4);
        *(uint4*)&As[0][lr0 * PITCH + lq0 * 8] = convert_pack(av0);
        *(uint4*)&As[0][lr1 * PITCH + lq1 * 8] = convert_pack(av1);
        *(uint4*)&Bs[0][lr0 * PITCH + lq0 * 8] = bv0;
        *(uint4*)&Bs[0][lr1 * PITCH + lq1 * 8] = bv1;
    }
    __syncthreads();

    for (int ch = 0; ch < 64; ch++) {
        const int s = ch & 1;
        float4 av0, av1;
        uint4  bv0, bv1;
        if (ch < 63) {
            const int k0 = (ch + 1) * 16;   // original k offset
            av0 = *(const float4*)(sx + (size_t)(bs + lr0) * FEAT + k0 + lq0 * 4);
            av1 = *(const float4*)(sx + (size_t)(bs + lr1) * FEAT + k0 + lq1 * 4);
            bv0 = *(const uint4*)(wt2 + (size_t)(bn + lr0) * FEAT + k0 + lq0 * 4);
            bv1 = *(const uint4*)(wt2 + (size_t)(bn + lr1) * FEAT + k0 + lq1 * 4);
        }

        // ---- compute on stage s ----
#pragma unroll
        for (int ks = 0; ks < 2; ks++) {
            uint32_t af[2][4];
#pragma unroll
            for (int t = 0; t < 2; t++) {
                int row = wm * 32 + t * 16 + a_row_off;
                int u   = 2 * ks + a_u_off;
                uint32_t addr = a_base[s] + (uint32_t)(row * 80 + u * 16);
                asm volatile(
                    "ldmatrix.sync.aligned.m8n8.x4.shared.b16 {%0,%1,%2,%3}, [%4];"
                    : "=r"(af[t][0]), "=r"(af[t][1]), "=r"(af[t][2]), "=r"(af[t][3])
                    : "r"(addr));
            }
            uint32_t bf[4][4];
#pragma unroll
            for (int np = 0; np < 4; np++) {
                int row = wn * 64 + np * 16 + b_row_off;
                int u   = 2 * ks + b_u_off;
                uint32_t addr = b_base[s] + (uint32_t)(row * 80 + u * 16);
                asm volatile(
                    "ldmatrix.sync.aligned.m8n8.x4.shared.b16 {%0,%1,%2,%3}, [%4];"
                    : "=r"(bf[np][0]), "=r"(bf[np][1]), "=r"(bf[np][2]), "=r"(bf[np][3])
                    : "r"(addr));
            }
#pragma unroll
            for (int t = 0; t < 2; t++)
#pragma unroll
                for (int nf = 0; nf < 8; nf++) {
                    uint32_t b0 = bf[nf >> 1][(nf & 1) * 2 + 0];
                    uint32_t b1 = bf[nf >> 1][(nf & 1) * 2 + 1];
                    asm volatile(
                        "mma.sync.aligned.m16n8k16.row.col.f32.bf16.bf16.f32 "
                        "{%0,%1,%2,%3}, {%4,%5,%6,%7}, {%8,%9}, {%0,%1,%2,%3};"
                        : "+f"(c[t][nf][0]), "+f"(c[t][nf][1]),
                          "+f"(c[t][nf][2]), "+f"(c[t][nf][3])
                        : "r"(af[t][0]), "r"(af[t][1]), "r"(af[t][2]), "r"(af[t][3]),
                          "r"(b0), "r"(b1));
                }
        }

        if (ch < 63) {
            const int ns = s ^ 1;
            *(uint4*)&As[ns][lr0 * PITCH + lq0 * 8] = convert_pack(av0);
            *(uint4*)&As[ns][lr1 * PITCH + lq1 * 8] = convert_pack(av1);
            *(uint4*)&Bs[ns][lr0 * PITCH + lq0 * 8] = bv0;
            *(uint4*)&Bs[ns][lr1 * PITCH + lq1 * 8] = bv1;
            __syncthreads();
        }
    }

    // epilogue: C frag -> g_sxp
#pragma unroll
    for (int t = 0; t < 2; t++) {
        int row0 = bs + wm * 32 + t * 16 + (lane >> 2);
        int col  = bn + wn * 64 + 2 * (lane & 3);
#pragma unroll
        for (int nf = 0; nf < 8; nf++) {
            int cc = col + nf * 8;
            *(float2*)(g_sxp + (size_t)row0 * PROJ + cc) =
                make_float2(c[t][nf][0], c[t][nf][1]);
            *(float2*)(g_sxp + (size_t)(row0 + 8) * PROJ + cc) =
                make_float2(c[t][nf][2], c[t][nf][3]);
        }
    }
}

// ---------------------------------------------------------------------------
// K3: ssq[j] = ||sxp_j||^2
// ---------------------------------------------------------------------------
__global__ void k_ssq(void) {
    int j    = blockIdx.x * 8 + (threadIdx.x >> 5);
    int lane = threadIdx.x & 31;
    const float4* row = (const float4*)(g_sxp + (size_t)j * PROJ);
    float s = 0.f;
#pragma unroll
    for (int q = 0; q < 2; q++) {
        float4 v = row[lane + 32 * q];
        s += v.x * v.x + v.y * v.y + v.z * v.z + v.w * v.w;
    }
#pragma unroll
    for (int o = 16; o; o >>= 1) s += __shfl_xor_sync(0xffffffffu, s, o);
    if (lane == 0) g_ssq[j] = s;
}

// ---------------------------------------------------------------------------
// K4: logits[b][j] = 2 * xq_b . sxp_j - ssq_j
// ---------------------------------------------------------------------------
__global__ void __launch_bounds__(256) k_logits(void) {
    __shared__ __align__(16) float xqT[PROJ][33];
    __shared__ __align__(16) float Ss[16][132];
    const int js  = blockIdx.x * 128;
    const int tid = threadIdx.x;
    const int tx  = tid & 15;
    const int ty  = tid >> 4;

    for (int i = tid; i < BATCH * PROJ; i += 256)
        xqT[i & 255][i >> 8] = g_xq[i];

    float c[2][8];
#pragma unroll
    for (int i = 0; i < 2; i++)
#pragma unroll
        for (int j = 0; j < 8; j++) c[i][j] = 0.f;

    for (int k0 = 0; k0 < PROJ; k0 += 16) {
        __syncthreads();
#pragma unroll
        for (int r = 0; r < 2; r++) {
            int idx = tid + r * 256;
            int row = idx >> 2;
            int kq  = (idx & 3) << 2;
            float4 v = *(const float4*)(g_sxp + (size_t)(js + row) * PROJ + k0 + kq);
            Ss[kq + 0][row] = v.x; Ss[kq + 1][row] = v.y;
            Ss[kq + 2][row] = v.z; Ss[kq + 3][row] = v.w;
        }
        __syncthreads();
#pragma unroll
        for (int k = 0; k < 16; k++) {
            float a0 = xqT[k0 + k][ty * 2];
            float a1 = xqT[k0 + k][ty * 2 + 1];
            float4 s0 = *(const float4*)&Ss[k][tx * 8];
            float4 s1 = *(const float4*)&Ss[k][tx * 8 + 4];
            float sv[8] = {s0.x, s0.y, s0.z, s0.w, s1.x, s1.y, s1.z, s1.w};
#pragma unroll
            for (int j = 0; j < 8; j++) {
                c[0][j] = fmaf(a0, sv[j], c[0][j]);
                c[1][j] = fmaf(a1, sv[j], c[1][j]);
            }
        }
    }
#pragma unroll
    for (int bi = 0; bi < 2; bi++) {
        int b = ty * 2 + bi;
#pragma unroll
        for (int h = 0; h < 2; h++) {
            int j0 = tx * 8 + h * 4;
            float4 o;
            o.x = 2.f * c[bi][h * 4 + 0] - g_ssq[js + j0 + 0];
            o.y = 2.f * c[bi][h * 4 + 1] - g_ssq[js + j0 + 1];
            o.z = 2.f * c[bi][h * 4 + 2] - g_ssq[js + j0 + 2];
            o.w = 2.f * c[bi][h * 4 + 3] - g_ssq[js + j0 + 3];
            *(float4*)(g_logits + (size_t)b * NSUP + js + j0) = o;
        }
    }
}

// ---------------------------------------------------------------------------
// K5: per-row softmax + class scatter + log
// ---------------------------------------------------------------------------
__global__ void __launch_bounds__(1024) k_out(const int* __restrict__ syw,
                                              float* __restrict__ out) {
    const int b = blockIdx.x;
    __shared__ float red[32];
    __shared__ float cls[NCLS];
    const int tid  = threadIdx.x;
    const int warp = tid >> 5, lane = tid & 31;

    for (int c = tid; c < NCLS; c += 1024) cls[c] = 0.f;

    const float* lr = g_logits + (size_t)b * NSUP;
    float l[8];
    float m = -3.4e38f;
#pragma unroll
    for (int q = 0; q < 8; q++) {
        l[q] = lr[q * 1024 + tid];
        m = fmaxf(m, l[q]);
    }
#pragma unroll
    for (int o = 16; o; o >>= 1) m = fmaxf(m, __shfl_xor_sync(0xffffffffu, m, o));
    if (lane == 0) red[warp] = m;
    __syncthreads();
    if (warp == 0) {
        float v = red[lane];
#pragma unroll
        for (int o = 16; o; o >>= 1) v = fmaxf(v, __shfl_xor_sync(0xffffffffu, v, o));
        if (lane == 0) red[0] = v;
    }
    __syncthreads();
    m = red[0];
    __syncthreads();

    float e[8];
    float s = 0.f;
#pragma unroll
    for (int q = 0; q < 8; q++) {
        e[q] = expf(l[q] - m);
        s += e[q];
    }
#pragma unroll
    for (int o = 16; o; o >>= 1) s += __shfl_xor_sync(0xffffffffu, s, o);
    if (lane == 0) red[warp] = s;
    __syncthreads();
    if (warp == 0) {
        float v = red[lane];
#pragma unroll
        for (int o = 16; o; o >>= 1) v += __shfl_xor_sync(0xffffffffu, v, o);
        if (lane == 0) red[0] = v;
    }
    __syncthreads();
    const float invZ = 1.f / red[0];
    const int is64 = g_sy_is64;

#pragma unroll
    for (int q = 0; q < 8; q++) {
        int j = q * 1024 + tid;
        int cidx = is64 ? syw[2 * j] : syw[j];
        atomicAdd(&cls[cidx], e[q]);
    }
    __syncthreads();
    for (int c = tid; c < NCLS; c += 1024)
        out[b * NCLS + c] = logf(cls[c] * invZ + 1e-12f);
}

// ---------------------------------------------------------------------------
extern "C" void kernel_launch(void* const* d_in, const int* in_sizes, int n_in,
                              void* d_out, int out_size) {
    const float* x = nullptr;
    const float* sx = nullptr;
    const float* W = nullptr;
    const void*  sy = nullptr;
    for (int i = 0; i < n_in; i++) {
        switch (in_sizes[i]) {
            case BATCH * FEAT: x  = (const float*)d_in[i]; break;
            case NSUP * FEAT:  sx = (const float*)d_in[i]; break;
            case FEAT * PROJ:  W  = (const float*)d_in[i]; break;
            case NSUP:         sy = d_in[i];               break;
            default: break;
        }
    }
    float* out = (float*)d_out;

    k_detect<<<1, 256>>>((const unsigned*)sy);
    k_wt<<<dim3(32, 8), 256>>>(W);
    k_zero_xq<<<8, 1024>>>();
    {
        dim3 g(BATCH, FEAT / 256);
        k_xq<<<g, 256>>>(x, W);
    }
    k_sxp_hmma<<<dim3(64, 2), 256>>>(sx);
    k_ssq<<<NSUP / 8, 256>>>();
    k_logits<<<NSUP / 128, 256>>>();
    k_out<<<BATCH, 1024>>>((const int*)sy, out);
}